// round 15
// baseline (speedup 1.0000x reference)
#include <cuda_runtime.h>
#include <cuda_fp16.h>
#include <mma.h>

using namespace nvcuda;

// Problem constants
#define B_   16
#define T_   1024
#define DIN  1024
#define UN   512
#define NG   2048          // 4*U
#define M_   (B_ * T_)     // 16384
#define NL   5
#define NREG 8             // h replication regions

// ---------------- scratch (static __device__, allocation-free) -------------
__device__ __align__(16) __half g_yh[2][(size_t)M_ * DIN];       // fp16 layer outputs (+x)
__device__ __align__(16) __half g_wh[(size_t)NL * 2 * DIN * NG]; // fp16 W
__device__ float g_h2[2][2][NREG][UN * B_];                      // tagged h (fp32), replicated

// ---------------- small helpers --------------------------------------------
__device__ __forceinline__ float sigm(float x) {
    return 1.0f / (1.0f + __expf(-x));
}
__device__ __forceinline__ void cp16(void* s, const void* g) {
    unsigned a = (unsigned)__cvta_generic_to_shared(s);
    asm volatile("cp.async.cg.shared.global [%0], [%1], 16;"
                 :: "r"(a), "l"(g) : "memory");
}
__device__ __forceinline__ void cp_commit() {
    asm volatile("cp.async.commit_group;" ::: "memory");
}
__device__ __forceinline__ void cp_wait1() {
    asm volatile("cp.async.wait_group 1;" ::: "memory");
}
__device__ __forceinline__ float4 ldv4_vol(const float4* p) {
    float4 v;
    asm volatile("ld.volatile.global.v4.f32 {%0,%1,%2,%3}, [%4];"
                 : "=f"(v.x), "=f"(v.y), "=f"(v.z), "=f"(v.w) : "l"(p) : "memory");
    return v;
}
__device__ __forceinline__ void st_vol(float* p, float v) {
    asm volatile("st.volatile.global.f32 [%0], %1;" :: "l"(p), "f"(v) : "memory");
}

// ---------------- fp16 pre-conversion (once per launch) ---------------------
__global__ void to_half(const float* __restrict__ in, __half* __restrict__ out,
                        size_t n4) {
    size_t i = (size_t)blockIdx.x * blockDim.x + threadIdx.x;
    size_t stride = (size_t)gridDim.x * blockDim.x;
    for (; i < n4; i += stride) {
        float4 v = ((const float4*)in)[i];
        __half2 a = __floats2half2_rn(v.x, v.y);
        __half2 b = __floats2half2_rn(v.z, v.w);
        *(uint2*)&out[i * 4] = make_uint2(*(unsigned*)&a, *(unsigned*)&b);
    }
}

// ---------------- fused recurrence + input projection ----------------------
// 128 CTAs x 256 thr: blocks 0..63 dir 0 (fwd), 64..127 dir 1 (rev).
// CTA owns 8 units (32 gate cols). ASYMMETRIC y@W split matched to warp roles:
//   warps 0-3 (gate/publish owners): y K-chunk  64 (4 ksteps, ~200cyc)
//   warps 4-7 (no gate duty):        y K-chunk 192 (12 ksteps, ~600cyc)
// -> both groups reach the h-poll at ~the same time, after peer publishes land.
// h transport: R6 tagged values (period-4 tags 2/4), 8-region replication,
// one __syncthreads/step, fused reduce+bias+gates. No standalone GEMM.
#define WPH  40                          // W smem row stride (halfs, 80B)
#define YST  34816                       // bytes per y stage (4x2304 + 4x6400)
#define OFF_W    0                       // half[1024*40]      81920 B
#define OFF_Y    81920                   // 2 stages          69632 B
#define OFF_HS   151552                  // half[512*16]      16384 B
#define OFF_RED  167936                  // float[2][8][512]  32768 B (Uh staging @init)
#define OFF_BC   200704                  // bias[32] + c_s[128] 640 B
#define REC_SMEM 201344

__global__ void __launch_bounds__(256, 1) lstm_rec(const float* __restrict__ Uh_l,
                                                   const __half* __restrict__ Wl,
                                                   const float* __restrict__ bl,
                                                   const __half* __restrict__ yin,
                                                   int y_sel, float* __restrict__ out) {
    extern __shared__ char sm[];
    __half* Ws   = (__half*)(sm + OFF_W);
    __half* h_s  = (__half*)(sm + OFF_HS);
    float*  red  = (float*)(sm + OFF_RED);
    __half* Uh_s = (__half*)(sm + OFF_RED);   // init-only staging, aliases red
    float*  bias_s = (float*)(sm + OFF_BC);
    float*  c_s  = (float*)(sm + OFF_BC + 128);

    const int tid = threadIdx.x;
    const int d = blockIdx.x >> 6;
    const int cb = blockIdx.x & 63;
    const int u0 = cb * 8;
    const int reg = cb >> 3;             // consumer octant -> region
    const int wid = tid >> 5, lane = tid & 31;
    const int k0 = wid << 6;             // h K-chunk (64) per warp
    const bool small = (wid < 4);        // gate-owner warps -> small y chunk
    const int k0y  = small ? (wid << 6) : (256 + (wid - 4) * 192);
    const int ypitch = small ? 72 : 200; // y row stride (halfs)
    const int woff = small ? wid * 2304 : 9216 + (wid - 4) * 6400;
    const int nsub = small ? 1 : 3;      // 64-wide subtiles per y chunk

    const float* Uh = Uh_l + (size_t)d * UN * NG;
    const __half* W = Wl + (size_t)d * DIN * NG;
    const float* bb = bl + d * NG;
    const bool final_layer = (y_sel == 2);
    __half* yout_h = (y_sel == 0) ? g_yh[0] : g_yh[1];

    // ---- init 1: stage Uh (fp16) into red-aliased area, load reg fragments -
    for (int i = tid; i < UN * 32; i += 256) {
        int k = i >> 5, c = i & 31;
        int g = c >> 3, j = c & 7;
        Uh_s[i] = __float2half_rn(Uh[(size_t)k * NG + g * UN + u0 + j]);
    }
    __syncthreads();
    wmma::fragment<wmma::matrix_b, 16, 16, 16, __half, wmma::row_major> bfr[4][2];
#pragma unroll
    for (int ks = 0; ks < 4; ++ks)
#pragma unroll
        for (int nt = 0; nt < 2; ++nt)
            wmma::load_matrix_sync(bfr[ks][nt], &Uh_s[(k0 + ks * 16) * 32 + nt * 16], 32);
    __syncthreads();

    // ---- init 2: stage W slice [1024 x 32cols] (smem col cl=g*8+j) ---------
    for (int i = tid; i < 4096; i += 256) {
        int k = i >> 2, g = i & 3;
        *(uint4*)&Ws[k * WPH + g * 8] =
            *(const uint4*)&W[(size_t)k * NG + g * UN + u0];
    }
    // bias + c-state + publish hin_0 zeros (tag 2.0)
    if (tid < 32) {
        int g = tid >> 3, j = tid & 7;
        bias_s[tid] = bb[g * UN + u0 + j];
    }
    if (tid < 128) {
        c_s[tid] = 0.0f;
        int ul = tid >> 4, b = tid & 15;
        float* base = &g_h2[d][0][0][(u0 + ul) * B_ + b];
#pragma unroll
        for (int r = 0; r < NREG; ++r) st_vol(base + r * (UN * B_), 2.0f);
    }

    // ---- y tile pipeline (per-warp private 2-stage cp.async) --------------
    // full per-warp chunk staged as nsub 64-wide subtiles (4 cp16/lane each)
    auto stage_y = [&](int stp, int buf) {
        int ty = d ? (T_ - 1 - stp) : stp;
        char* yb = sm + OFF_Y + buf * YST + woff;
        for (int sub = 0; sub < nsub; ++sub) {
#pragma unroll
            for (int i = 0; i < 4; ++i) {
                int idx = lane + i * 32;
                int row = idx >> 3, col = sub * 64 + ((idx & 7) << 3);
                cp16(yb + row * (ypitch * 2) + col * 2,
                     yin + (((size_t)(row << 10) + ty) << 10) + k0y + col);
            }
        }
        cp_commit();
    };
    stage_y(0, 0);
    stage_y(1, 1);
    __syncthreads();   // Ws/bias visible; zeros published

    for (int step = 0; step < T_; ++step) {
        const int tt = d ? (T_ - 1 - step) : step;
        const int p = step & 1;
        const float e  = 2.0f + 2.0f * (float)((step >> 1) & 1);
        const float e1 = e + 1.0f;       // inclusive (h can round to 1.0)

        // 1) y[t] tile ready (own group), warp-converged
        cp_wait1();
        __syncwarp();
        const __half* yb = (const __half*)(sm + OFF_Y + p * YST + woff);

        // 2) y @ W partial (asymmetric kstep count)
        wmma::fragment<wmma::accumulator, 16, 16, 16, float> a0a, a0b, a1a, a1b;
        wmma::fill_fragment(a0a, 0.0f); wmma::fill_fragment(a0b, 0.0f);
        wmma::fill_fragment(a1a, 0.0f); wmma::fill_fragment(a1b, 0.0f);
        if (small) {
#pragma unroll
            for (int ks = 0; ks < 4; ks += 2) {
                wmma::fragment<wmma::matrix_a, 16, 16, 16, __half, wmma::row_major> ya0, ya1;
                wmma::fragment<wmma::matrix_b, 16, 16, 16, __half, wmma::row_major> wb0, wb1;
                wmma::load_matrix_sync(ya0, &yb[ks * 16], 72);
                wmma::load_matrix_sync(ya1, &yb[(ks + 1) * 16], 72);
                wmma::load_matrix_sync(wb0, &Ws[(k0y + ks * 16) * WPH], WPH);
                wmma::load_matrix_sync(wb1, &Ws[(k0y + ks * 16) * WPH + 16], WPH);
                wmma::mma_sync(a0a, ya0, wb0, a0a);
                wmma::mma_sync(a1a, ya0, wb1, a1a);
                wmma::load_matrix_sync(wb0, &Ws[(k0y + (ks + 1) * 16) * WPH], WPH);
                wmma::load_matrix_sync(wb1, &Ws[(k0y + (ks + 1) * 16) * WPH + 16], WPH);
                wmma::mma_sync(a0b, ya1, wb0, a0b);
                wmma::mma_sync(a1b, ya1, wb1, a1b);
            }
        } else {
#pragma unroll
            for (int ks = 0; ks < 12; ks += 2) {
                wmma::fragment<wmma::matrix_a, 16, 16, 16, __half, wmma::row_major> ya0, ya1;
                wmma::fragment<wmma::matrix_b, 16, 16, 16, __half, wmma::row_major> wb0, wb1;
                wmma::load_matrix_sync(ya0, &yb[ks * 16], 200);
                wmma::load_matrix_sync(ya1, &yb[(ks + 1) * 16], 200);
                wmma::load_matrix_sync(wb0, &Ws[(k0y + ks * 16) * WPH], WPH);
                wmma::load_matrix_sync(wb1, &Ws[(k0y + ks * 16) * WPH + 16], WPH);
                wmma::mma_sync(a0a, ya0, wb0, a0a);
                wmma::mma_sync(a1a, ya0, wb1, a1a);
                wmma::load_matrix_sync(wb0, &Ws[(k0y + (ks + 1) * 16) * WPH], WPH);
                wmma::load_matrix_sync(wb1, &Ws[(k0y + (ks + 1) * 16) * WPH + 16], WPH);
                wmma::mma_sync(a0b, ya1, wb0, a0b);
                wmma::mma_sync(a1b, ya1, wb1, a1b);
            }
        }

        // 3) prefetch y[t+2] into the buffer just consumed (warp-private)
        if (step + 2 < T_) stage_y(step + 2, p);
        else cp_commit();   // keep group accounting uniform

        // 4) per-warp: spin-load own 64x16 h slice from own region (R6 exact)
        {
            const float4* src = (const float4*)(g_h2[d][p][reg]) + k0 * 4;
            float4 v[8];
            unsigned done = 0;
            while (done != 0xFFu) {
#pragma unroll
                for (int i = 0; i < 8; ++i)
                    if (!((done >> i) & 1)) v[i] = ldv4_vol(src + lane + i * 32);
#pragma unroll
                for (int i = 0; i < 8; ++i)
                    if (!((done >> i) & 1)) {
                        bool ok = (v[i].x >= e) & (v[i].x <= e1) &
                                  (v[i].y >= e) & (v[i].y <= e1) &
                                  (v[i].z >= e) & (v[i].z <= e1) &
                                  (v[i].w >= e) & (v[i].w <= e1);
                        if (ok) done |= 1u << i;
                    }
            }
#pragma unroll
            for (int i = 0; i < 8; ++i) {
                int idx = k0 * 4 + lane + i * 32;     // float4 index over [unit][b]
                int k = idx >> 2, q4 = idx & 3;
                __half2 p0 = __floats2half2_rn(v[i].x - e, v[i].y - e);
                __half2 p1 = __floats2half2_rn(v[i].z - e, v[i].w - e);
                __half2* dst = (__half2*)&h_s[k * 16 + q4 * 4];
                dst[0] = p0;
                dst[1] = p1;
            }
            __syncwarp();
        }

        // 5) h @ Uh partial into the same accumulators (R6 exact)
        {
#pragma unroll
            for (int ks = 0; ks < 4; ks += 2) {
                wmma::fragment<wmma::matrix_a, 16, 16, 16, __half, wmma::col_major> af0, af1;
                wmma::load_matrix_sync(af0, &h_s[(k0 + ks * 16) * 16], 16);
                wmma::load_matrix_sync(af1, &h_s[(k0 + (ks + 1) * 16) * 16], 16);
                wmma::mma_sync(a0a, af0, bfr[ks][0], a0a);
                wmma::mma_sync(a1a, af0, bfr[ks][1], a1a);
                wmma::mma_sync(a0b, af1, bfr[ks + 1][0], a0b);
                wmma::mma_sync(a1b, af1, bfr[ks + 1][1], a1b);
            }
#pragma unroll
            for (int i = 0; i < a0a.num_elements; ++i) {
                a0a.x[i] += a0b.x[i];
                a1a.x[i] += a1b.x[i];
            }
            float* rb = &red[(p * 8 + wid) * 512];
            wmma::store_matrix_sync(rb, a0a, 16, wmma::mem_col_major);
            wmma::store_matrix_sync(rb + 256, a1a, 16, wmma::mem_col_major);
        }
        __syncthreads();   // the ONLY barrier per step

        // 6) fused reduce + bias + gates + publish (warps 0-3, R6 pattern)
        if (tid < 128) {
            int ul = tid >> 4, b = tid & 15;
            float v0 = bias_s[0 * 8 + ul];
            float v1 = bias_s[1 * 8 + ul];
            float v2 = bias_s[2 * 8 + ul];
            float v3 = bias_s[3 * 8 + ul];
#pragma unroll
            for (int w = 0; w < 8; ++w) {
                const float* rb = &red[(p * 8 + w) * 512];
                v0 += rb[(0 * 8 + ul) * 16 + b];
                v1 += rb[(1 * 8 + ul) * 16 + b];
                v2 += rb[(2 * 8 + ul) * 16 + b];
                v3 += rb[(3 * 8 + ul) * 16 + b];
            }
            float cc = sigm(v1) * c_s[tid] + sigm(v0) * sigm(v2);
            c_s[tid] = cc;
            float h = sigm(v3) * sigm(cc);
            if (step < T_ - 1) {
                float tv = h + 2.0f + 2.0f * (float)(((step + 1) >> 1) & 1);
                float* base = &g_h2[d][(step + 1) & 1][0][(u0 + ul) * B_ + b];
#pragma unroll
                for (int r = 0; r < NREG; ++r) st_vol(base + r * (UN * B_), tv);
            }
            size_t yidx = ((size_t)(b << 10) + tt) * (2 * UN) + (d << 9) + u0 + ul;
            if (final_layer) out[yidx] = h;
            else             yout_h[yidx] = __float2half_rn(h);
        }
        // red double-buffered by p; h_s & y tiles warp-private; no trailing barrier
    }
}

// ---------------- launcher ---------------------------------------------------
extern "C" void kernel_launch(void* const* d_in, const int* in_sizes, int n_in,
                              void* d_out, int out_size) {
    (void)in_sizes; (void)n_in; (void)out_size;
    const float* x  = (const float*)d_in[0];
    const float* W  = (const float*)d_in[1];
    const float* Uh = (const float*)d_in[2];
    const float* bb = (const float*)d_in[3];
    float* out = (float*)d_out;

    cudaFuncSetAttribute(lstm_rec, cudaFuncAttributeMaxDynamicSharedMemorySize, REC_SMEM);

    __half* g_yh_p; cudaGetSymbolAddress((void**)&g_yh_p, g_yh);
    __half* g_wh_p; cudaGetSymbolAddress((void**)&g_wh_p, g_wh);
    __half* xh = g_yh_p + (size_t)M_ * DIN;   // g_yh[1] holds fp16 x (layer 0 input)
    to_half<<<1024, 256>>>(x, xh, (size_t)M_ * DIN / 4);
    to_half<<<2048, 256>>>(W, g_wh_p, (size_t)NL * 2 * DIN * NG / 4);

    for (int l = 0; l < NL; ++l) {
        const __half* yin = (l == 0) ? xh : (g_yh_p + (size_t)((l - 1) & 1) * M_ * DIN);
        int y_sel = (l == NL - 1) ? 2 : (l & 1);
        lstm_rec<<<128, 256, REC_SMEM>>>(Uh + (size_t)l * 2 * UN * NG,
                                         g_wh_p + (size_t)l * 2 * DIN * NG,
                                         bb + (size_t)l * 2 * NG,
                                         yin, y_sel, out);
    }
}

// round 16
// speedup vs baseline: 1.0516x; 1.0516x over previous
#include <cuda_runtime.h>
#include <cuda_fp16.h>
#include <mma.h>

using namespace nvcuda;

// Problem constants
#define B_   16
#define T_   1024
#define DIN  1024
#define UN   512
#define NG   2048          // 4*U
#define M_   (B_ * T_)     // 16384
#define NL   5
#define NREG 8             // h replication regions

// ---------------- scratch (static __device__, allocation-free) -------------
__device__ __align__(16) __half g_xz[2][(size_t)M_ * NG];        // fp16 input projections
__device__ __align__(16) __half g_yh[2][(size_t)M_ * DIN];       // fp16 layer outputs (+x)
__device__ __align__(16) __half g_wh[(size_t)NL * 2 * DIN * NG]; // fp16 W
__device__ float g_h2[2][2][NREG][UN * B_];                      // tagged h (fp32), replicated

// ---------------- small helpers --------------------------------------------
__device__ __forceinline__ float sigm(float x) {
    return 1.0f / (1.0f + __expf(-x));
}
__device__ __forceinline__ void cp16(void* s, const void* g) {
    unsigned a = (unsigned)__cvta_generic_to_shared(s);
    asm volatile("cp.async.cg.shared.global [%0], [%1], 16;"
                 :: "r"(a), "l"(g) : "memory");
}
__device__ __forceinline__ void cp_commit() {
    asm volatile("cp.async.commit_group;" ::: "memory");
}
__device__ __forceinline__ void cp_wait1() {
    asm volatile("cp.async.wait_group 1;" ::: "memory");
}
__device__ __forceinline__ float4 ldv4_vol(const float4* p) {
    float4 v;
    asm volatile("ld.volatile.global.v4.f32 {%0,%1,%2,%3}, [%4];"
                 : "=f"(v.x), "=f"(v.y), "=f"(v.z), "=f"(v.w) : "l"(p) : "memory");
    return v;
}
__device__ __forceinline__ void st_vol(float* p, float v) {
    asm volatile("st.volatile.global.f32 [%0], %1;" :: "l"(p), "f"(v) : "memory");
}
__device__ __forceinline__ void ldm4(unsigned* r, unsigned addr) {
    asm volatile("ldmatrix.sync.aligned.m8n8.x4.shared.b16 {%0,%1,%2,%3}, [%4];"
                 : "=r"(r[0]), "=r"(r[1]), "=r"(r[2]), "=r"(r[3]) : "r"(addr));
}
__device__ __forceinline__ void ldm4t(unsigned* r, unsigned addr) {
    asm volatile("ldmatrix.sync.aligned.m8n8.x4.trans.shared.b16 {%0,%1,%2,%3}, [%4];"
                 : "=r"(r[0]), "=r"(r[1]), "=r"(r[2]), "=r"(r[3]) : "r"(addr));
}
__device__ __forceinline__ void mma16816(float* d, const unsigned* a, const unsigned* b) {
    asm volatile("mma.sync.aligned.m16n8k16.row.col.f32.f16.f16.f32 "
                 "{%0,%1,%2,%3}, {%4,%5,%6,%7}, {%8,%9}, {%0,%1,%2,%3};"
                 : "+f"(d[0]), "+f"(d[1]), "+f"(d[2]), "+f"(d[3])
                 : "r"(a[0]), "r"(a[1]), "r"(a[2]), "r"(a[3]), "r"(b[0]), "r"(b[1]));
}

// ---------------- fp16 pre-conversion (once per launch) ---------------------
__global__ void to_half(const float* __restrict__ in, __half* __restrict__ out,
                        size_t n4) {
    size_t i = (size_t)blockIdx.x * blockDim.x + threadIdx.x;
    size_t stride = (size_t)gridDim.x * blockDim.x;
    for (; i < n4; i += stride) {
        float4 v = ((const float4*)in)[i];
        __half2 a = __floats2half2_rn(v.x, v.y);
        __half2 b = __floats2half2_rn(v.z, v.w);
        *(uint2*)&out[i * 4] = make_uint2(*(unsigned*)&a, *(unsigned*)&b);
    }
}

// ---------------- input-projection GEMM (ldmatrix + mma.16816, BK=64) ------
// R11 core (proven): 128x128 CTA tile, warp tile 64x32, 3-stage cp.async,
// 256 thr, 2 CTAs/SM. Changes: BK 32->64 (halves barrier count; 16 k-tiles),
// fp16 epilogue (halves xz traffic).
#define BM 128
#define BN 128
#define BK 64
#define APH 72    // A row stride (halfs) = 144B = 9x16B: ldmatrix conflict-free
#define BPH 136   // B row stride (halfs) = 272B = 17x16B: conflict-free
#define ASZH (BM * APH)      // 9216 halfs
#define BSZH (BK * BPH)      // 8704 halfs
#define STAGE_H (ASZH + BSZH)
#define GEMM_SMEM (3 * STAGE_H * 2 + BN * 4)   // 108032 B

__global__ void __launch_bounds__(256, 2) lstm_gemm(const __half* __restrict__ A,
                                                    const __half* __restrict__ Wl,
                                                    const float* __restrict__ bl) {
    extern __shared__ char gsm[];
    __half* stg = (__half*)gsm;
    float* Bias = (float*)(gsm + 3 * STAGE_H * 2);

    const int d = blockIdx.z;
    const __half* W = Wl + (size_t)d * DIN * NG;
    const float* bias = bl + d * NG;
    __half* C = g_xz[d];

    const int tid = threadIdx.x;
    const int lane = tid & 31;
    const int bn0 = blockIdx.x * BN;
    const int bm0 = blockIdx.y * BM;

    for (int i = tid; i < BN; i += 256) Bias[i] = bias[bn0 + i];

    const int wid = tid >> 5;
    const int wr = wid >> 2;   // 0..1 -> 64-row slab
    const int wc = wid & 3;    // 0..3 -> 32-col slab

    // ldmatrix lane roles
    const int a_row = lane & 15;
    const int a_k   = (lane >> 4) << 3;
    const int b_k   = lane & 15;
    const int b_n   = (lane >> 4) << 3;

    const __half* Abase = A + (size_t)bm0 * DIN;
    const __half* Bbase = W + bn0;

    auto issue = [&](int kt) {
        int s = kt % 3;
        __half* Ad = stg + s * STAGE_H;
        __half* Bd = Ad + ASZH;
        const __half* Ag = Abase + kt * BK;
        // A: 128 rows x 64 halfs = 1024 chunks -> 4/thread
#pragma unroll
        for (int i = 0; i < 4; ++i) {
            int id = tid + i * 256;
            int r = id >> 3, ch = (id & 7) << 3;
            cp16(&Ad[r * APH + ch], &Ag[(size_t)r * DIN + ch]);
        }
        const __half* Bg = Bbase + (size_t)kt * BK * NG;
        // B: 64 rows x 128 halfs = 1024 chunks -> 4/thread
#pragma unroll
        for (int i = 0; i < 4; ++i) {
            int id = tid + i * 256;
            int r = id >> 4, ch = (id & 15) << 3;
            cp16(&Bd[r * BPH + ch], &Bg[(size_t)r * NG + ch]);
        }
        cp_commit();
    };

    issue(0);
    issue(1);
    __syncthreads();   // Bias visible

    // accumulators: 4 m-tiles x 4 n8-tiles x 4 regs, bias-initialized
    float acc[4][4][4];
    {
        int cbase = wc * 32 + ((lane & 3) << 1);
#pragma unroll
        for (int nn = 0; nn < 4; ++nn) {
            float b0 = Bias[cbase + nn * 8];
            float b1 = Bias[cbase + nn * 8 + 1];
#pragma unroll
            for (int mm = 0; mm < 4; ++mm) {
                acc[mm][nn][0] = b0; acc[mm][nn][1] = b1;
                acc[mm][nn][2] = b0; acc[mm][nn][3] = b1;
            }
        }
    }

    const int NT = DIN / BK;   // 16
    for (int kt = 0; kt < NT; ++kt) {
        cp_wait1();            // stage kt resident (kt+1 may be in flight)
        __syncthreads();       // protects stage (kt+2)%3: last read at iter kt-1
        if (kt + 2 < NT) issue(kt + 2);

        int s = kt % 3;
        __half* Ab = stg + s * STAGE_H;
        __half* Bb = Ab + ASZH;
        unsigned abase = (unsigned)__cvta_generic_to_shared(Ab);
        unsigned bbase = (unsigned)__cvta_generic_to_shared(Bb);

#pragma unroll
        for (int kk = 0; kk < 4; ++kk) {
            unsigned af[4][4];
#pragma unroll
            for (int mm = 0; mm < 4; ++mm)
                ldm4(af[mm], abase +
                     (((wr * 64 + mm * 16 + a_row) * APH + kk * 16 + a_k) << 1));
            unsigned bf[2][4];
#pragma unroll
            for (int nh = 0; nh < 2; ++nh)
                ldm4t(bf[nh], bbase +
                      (((kk * 16 + b_k) * BPH + wc * 32 + nh * 16 + b_n) << 1));
#pragma unroll
            for (int mm = 0; mm < 4; ++mm)
#pragma unroll
                for (int nn = 0; nn < 4; ++nn)
                    mma16816(acc[mm][nn], af[mm], &bf[nn >> 1][(nn & 1) << 1]);
        }
        // no trailing barrier: next iter's leading barrier is the hazard edge
    }

    // epilogue: mma c-layout -> row-major fp16 C
#pragma unroll
    for (int mm = 0; mm < 4; ++mm) {
        int row = bm0 + wr * 64 + mm * 16 + (lane >> 2);
#pragma unroll
        for (int nn = 0; nn < 4; ++nn) {
            int col = bn0 + wc * 32 + nn * 8 + ((lane & 3) << 1);
            __half2 h01 = __floats2half2_rn(acc[mm][nn][0], acc[mm][nn][1]);
            __half2 h23 = __floats2half2_rn(acc[mm][nn][2], acc[mm][nn][3]);
            *(__half2*)&C[(size_t)row * NG + col] = h01;
            *(__half2*)&C[(size_t)(row + 8) * NG + col] = h23;
        }
    }
}

// ---------------- persistent bidirectional recurrence (R6/R11, frozen) -----
// 128 CTAs x 256 thr. CTA owns 8 units; 8-warp K-split; tagged-h transport
// (period-4 tags 2/4); one __syncthreads/step; fused reduce+gates.
// Only change vs R11: xz read as fp16 (half2 -> float2).
#define OFF_HS   0                       // half[512*16]        16384 B
#define OFF_RED  16384                   // float[2][8][512]    32768 B (col-major ldm16)
#define OFF_XZ   49152                   // float[2][16*36]      4608 B
#define OFF_CS   53760                   // float[128]            512 B
#define REC_SMEM 54272                   // Uh fp16 staging (32KB) aliases [0,32K)

__global__ void __launch_bounds__(256, 1) lstm_rec(const float* __restrict__ Uh_l,
                                                   int y_sel, float* __restrict__ out) {
    extern __shared__ char sm[];
    __half* Uh_s = (__half*)(sm);        // init-only staging (aliases h_s + red)
    __half* h_s  = (__half*)(sm + OFF_HS);
    float* red  = (float*)(sm + OFF_RED);
    float* xz_s = (float*)(sm + OFF_XZ);
    float* c_s  = (float*)(sm + OFF_CS);

    const int tid = threadIdx.x;
    const int d = blockIdx.x >> 6;
    const int cb = blockIdx.x & 63;
    const int u0 = cb * 8;
    const int reg = cb >> 3;             // consumer octant -> region
    const int wid = tid >> 5, lane = tid & 31;
    const int k0 = wid << 6;             // 64-wide K chunk per warp

    const float* Uh = Uh_l + (size_t)d * UN * NG;
    const __half* xz = g_xz[d];
    const bool final_layer = (y_sel == 2);
    __half* yout_h = (y_sel == 0) ? g_yh[0] : g_yh[1];

    // ---- init: stage Uh (fp16) and load register fragments ----
    for (int i = tid; i < UN * 32; i += 256) {
        int k = i >> 5, c = i & 31;
        int g = c >> 3, j = c & 7;
        Uh_s[i] = __float2half_rn(Uh[(size_t)k * NG + g * UN + u0 + j]);
    }
    __syncthreads();

    wmma::fragment<wmma::matrix_b, 16, 16, 16, __half, wmma::row_major> bfr[4][2];
#pragma unroll
    for (int ks = 0; ks < 4; ++ks)
#pragma unroll
        for (int nt = 0; nt < 2; ++nt)
            wmma::load_matrix_sync(bfr[ks][nt], &Uh_s[(k0 + ks * 16) * 32 + nt * 16], 32);
    __syncthreads();

    // publish hin_0 = zeros (tag 2.0) into all regions; c = 0
    if (tid < 128) {
        c_s[tid] = 0.0f;
        int ul = tid >> 4, b = tid & 15;
        float* base = &g_h2[d][0][0][(u0 + ul) * B_ + b];
#pragma unroll
        for (int r = 0; r < NREG; ++r) st_vol(base + r * (UN * B_), 2.0f);
    }
    __syncthreads();

    for (int step = 0; step < T_; ++step) {
        const int tt = d ? (T_ - 1 - step) : step;
        const int p = step & 1;
        const float e  = 2.0f + 2.0f * (float)((step >> 1) & 1);
        const float e1 = e + 1.0f;       // inclusive (h can round to 1.0)

        // 1) xz for this timestep -> regs (fp16 -> fp32)
        float2 xv;
        {
            int b = tid >> 4, q = tid & 15;
            int c = q << 1, g = c >> 3, j = c & 7;
            __half2 xh2 = *(const __half2*)&xz[((size_t)(b << 10) + tt) * NG + g * UN + u0 + j];
            xv = __half22float2(xh2);
        }

        // 2) per-warp: spin-load own 64x16 h slice from own region
        float4 v[8];
        {
            const float4* src = (const float4*)(g_h2[d][p][reg]) + k0 * 4;
            unsigned done = 0;
            while (done != 0xFFu) {
#pragma unroll
                for (int i = 0; i < 8; ++i)
                    if (!((done >> i) & 1)) v[i] = ldv4_vol(src + lane + i * 32);
#pragma unroll
                for (int i = 0; i < 8; ++i)
                    if (!((done >> i) & 1)) {
                        bool ok = (v[i].x >= e) & (v[i].x <= e1) &
                                  (v[i].y >= e) & (v[i].y <= e1) &
                                  (v[i].z >= e) & (v[i].z <= e1) &
                                  (v[i].w >= e) & (v[i].w <= e1);
                        if (ok) done |= 1u << i;
                    }
            }
            // deswizzle -> fp16 smem [k][b] (col-major A, ldm 16)
#pragma unroll
            for (int i = 0; i < 8; ++i) {
                int idx = k0 * 4 + lane + i * 32;     // float4 index over [unit][b]
                int k = idx >> 2, q4 = idx & 3;
                __half2 p0 = __floats2half2_rn(v[i].x - e, v[i].y - e);
                __half2 p1 = __floats2half2_rn(v[i].z - e, v[i].w - e);
                __half2* dst = (__half2*)&h_s[k * 16 + q4 * 4];
                dst[0] = p0;
                dst[1] = p1;
            }
            __syncwarp();
        }

        // 3) xz -> smem buffer p
        {
            int b = tid >> 4, c = (tid & 15) << 1;
            *(float2*)&xz_s[p * 576 + b * 36 + c] = xv;
        }

        // 4) per-warp fp16 MMA over its 64-wide K chunk; col-major store
        {
            wmma::fragment<wmma::accumulator, 16, 16, 16, float> a0a, a0b, a1a, a1b;
            wmma::fill_fragment(a0a, 0.0f); wmma::fill_fragment(a0b, 0.0f);
            wmma::fill_fragment(a1a, 0.0f); wmma::fill_fragment(a1b, 0.0f);
#pragma unroll
            for (int ks = 0; ks < 4; ks += 2) {
                wmma::fragment<wmma::matrix_a, 16, 16, 16, __half, wmma::col_major> af0, af1;
                wmma::load_matrix_sync(af0, &h_s[(k0 + ks * 16) * 16], 16);
                wmma::load_matrix_sync(af1, &h_s[(k0 + (ks + 1) * 16) * 16], 16);
                wmma::mma_sync(a0a, af0, bfr[ks][0], a0a);
                wmma::mma_sync(a1a, af0, bfr[ks][1], a1a);
                wmma::mma_sync(a0b, af1, bfr[ks + 1][0], a0b);
                wmma::mma_sync(a1b, af1, bfr[ks + 1][1], a1b);
            }
#pragma unroll
            for (int i = 0; i < a0a.num_elements; ++i) {
                a0a.x[i] += a0b.x[i];
                a1a.x[i] += a1b.x[i];
            }
            float* rb = &red[(p * 8 + wid) * 512];
            wmma::store_matrix_sync(rb, a0a, 16, wmma::mem_col_major);
            wmma::store_matrix_sync(rb + 256, a1a, 16, wmma::mem_col_major);
        }
        __syncthreads();   // the ONLY barrier per step

        // 5) fused reduce + gates + publish (warps 0-3)
        if (tid < 128) {
            int ul = tid >> 4, b = tid & 15;
            float v0 = xz_s[p * 576 + b * 36 + 0 * 8 + ul];
            float v1 = xz_s[p * 576 + b * 36 + 1 * 8 + ul];
            float v2 = xz_s[p * 576 + b * 36 + 2 * 8 + ul];
            float v3 = xz_s[p * 576 + b * 36 + 3 * 8 + ul];
#pragma unroll
            for (int w = 0; w < 8; ++w) {
                const float* rb = &red[(p * 8 + w) * 512];
                v0 += rb[(0 * 8 + ul) * 16 + b];
                v1 += rb[(1 * 8 + ul) * 16 + b];
                v2 += rb[(2 * 8 + ul) * 16 + b];
                v3 += rb[(3 * 8 + ul) * 16 + b];
            }
            float cc = sigm(v1) * c_s[tid] + sigm(v0) * sigm(v2);
            c_s[tid] = cc;
            float h = sigm(v3) * sigm(cc);
            if (step < T_ - 1) {
                float tv = h + 2.0f + 2.0f * (float)(((step + 1) >> 1) & 1);
                float* base = &g_h2[d][(step + 1) & 1][0][(u0 + ul) * B_ + b];
#pragma unroll
                for (int r = 0; r < NREG; ++r) st_vol(base + r * (UN * B_), tv);
            }
            size_t yidx = ((size_t)(b << 10) + tt) * (2 * UN) + (d << 9) + u0 + ul;
            if (final_layer) out[yidx] = h;
            else             yout_h[yidx] = __float2half_rn(h);
        }
        // red/xz double-buffered; h_s warp-private; no trailing barrier
    }
}

// ---------------- launcher ---------------------------------------------------
extern "C" void kernel_launch(void* const* d_in, const int* in_sizes, int n_in,
                              void* d_out, int out_size) {
    (void)in_sizes; (void)n_in; (void)out_size;
    const float* x  = (const float*)d_in[0];
    const float* W  = (const float*)d_in[1];
    const float* Uh = (const float*)d_in[2];
    const float* bb = (const float*)d_in[3];
    float* out = (float*)d_out;

    cudaFuncSetAttribute(lstm_gemm, cudaFuncAttributeMaxDynamicSharedMemorySize, GEMM_SMEM);
    cudaFuncSetAttribute(lstm_rec,  cudaFuncAttributeMaxDynamicSharedMemorySize, REC_SMEM);

    __half* g_yh_p; cudaGetSymbolAddress((void**)&g_yh_p, g_yh);
    __half* g_wh_p; cudaGetSymbolAddress((void**)&g_wh_p, g_wh);
    __half* xh = g_yh_p + (size_t)M_ * DIN;   // g_yh[1] holds fp16 x
    to_half<<<1024, 256>>>(x, xh, (size_t)M_ * DIN / 4);
    to_half<<<2048, 256>>>(W, g_wh_p, (size_t)NL * 2 * DIN * NG / 4);

    dim3 ggrid(NG / BN, M_ / BM, 2);
    for (int l = 0; l < NL; ++l) {
        const __half* A = (l == 0) ? xh : (g_yh_p + (size_t)((l & 1) ^ 1) * M_ * DIN);
        lstm_gemm<<<ggrid, 256, GEMM_SMEM>>>(A,
                                             g_wh_p + (size_t)l * 2 * DIN * NG,
                                             bb + (size_t)l * 2 * NG);
        int y_sel = (l == NL - 1) ? 2 : (l & 1);
        lstm_rec<<<128, 256, REC_SMEM>>>(Uh + (size_t)l * 2 * UN * NG, y_sel, out);
    }
}